// round 2
// baseline (speedup 1.0000x reference)
#include <cuda_runtime.h>
#include <cuda_bf16.h>

#define BATCH 8192
#define DIM   16
#define DIM1  48
#define TTH   20
#define VOCAB 32000

// Scratch (no runtime allocation allowed)
__device__ float g_o[BATCH * DIM];        // stage-1 output o[b][k]
__device__ float g_et[DIM * VOCAB];       // transposed embed: g_et[k][e]

// ---------------------------------------------------------------------------
// packed f32x2 helpers
// ---------------------------------------------------------------------------
__device__ __forceinline__ unsigned long long f2fma(unsigned long long a,
                                                    unsigned long long b,
                                                    unsigned long long c) {
    unsigned long long d;
    asm("fma.rn.f32x2 %0, %1, %2, %3;" : "=l"(d) : "l"(a), "l"(b), "l"(c));
    return d;
}
__device__ __forceinline__ unsigned long long fdup(float x) {
    unsigned long long d;
    asm("mov.b64 %0, {%1, %1};" : "=l"(d) : "f"(x));
    return d;
}

// ---------------------------------------------------------------------------
// Kernel 0: transpose embed_w [VOCAB,16] -> g_et [16][VOCAB]
// ---------------------------------------------------------------------------
__global__ void k_transpose(const float* __restrict__ E) {
    int idx = blockIdx.x * blockDim.x + threadIdx.x;
    if (idx < DIM * VOCAB) {
        int k = idx / VOCAB;
        int e = idx - k * VOCAB;
        g_et[idx] = E[e * DIM + k];
    }
}

// ---------------------------------------------------------------------------
// Stage 1: fused tiny MLP, one thread per batch row
// ---------------------------------------------------------------------------
__device__ __forceinline__ void ln_silu(float* h, const float* g, const float* bt) {
    float mu = 0.f;
#pragma unroll
    for (int i = 0; i < DIM1; i++) mu += h[i];
    mu *= (1.0f / DIM1);
    float var = 0.f;
#pragma unroll
    for (int i = 0; i < DIM1; i++) { float d = h[i] - mu; var += d * d; }
    var *= (1.0f / DIM1);
    float r = rsqrtf(var + 1e-5f);
#pragma unroll
    for (int i = 0; i < DIM1; i++) {
        float y = (h[i] - mu) * r * g[i] + bt[i];
        h[i] = y / (1.0f + expf(-y));
    }
}

__global__ __launch_bounds__(64) void k_stage1(
    const float* __restrict__ we,  const float* __restrict__ ctx,
    const float* __restrict__ th,
    const float* __restrict__ WI1, const float* __restrict__ bI1,
    const float* __restrict__ WA1, const float* __restrict__ bA1,
    const float* __restrict__ WM1, const float* __restrict__ bM1,
    const float* __restrict__ WM2, const float* __restrict__ bM2,
    const float* __restrict__ WM3, const float* __restrict__ bM3,
    const float* __restrict__ lng, const float* __restrict__ lnb,
    const float* __restrict__ WO1, const float* __restrict__ bO1)
{
    __shared__ float sM1[DIM1 * 80];
    __shared__ float sM2[DIM1 * 112];
    __shared__ float sM3[DIM1 * DIM1];
    __shared__ float sb1[DIM1], sb2[DIM1], sb3[DIM1], sg[DIM1], sbt[DIM1];

    int tid = threadIdx.x;
    for (int i = tid; i < DIM1 * 80;  i += 64) sM1[i] = WM1[i];
    for (int i = tid; i < DIM1 * 112; i += 64) sM2[i] = WM2[i];
    for (int i = tid; i < DIM1 * DIM1; i += 64) sM3[i] = WM3[i];
    if (tid < DIM1) {
        sb1[tid] = bM1[tid]; sb2[tid] = bM2[tid]; sb3[tid] = bM3[tid];
        sg[tid] = lng[tid];  sbt[tid] = lnb[tid];
    }
    __syncthreads();

    int b = blockIdx.x * 64 + tid;
    if (b >= BATCH) return;

    // load inputs
    float x[DIM], c[DIM];
    {
        const float4* xp = (const float4*)&we[b * DIM];
        const float4* cp = (const float4*)&ctx[b * DIM];
#pragma unroll
        for (int q = 0; q < 4; q++) {
            float4 v = xp[q]; x[q*4+0]=v.x; x[q*4+1]=v.y; x[q*4+2]=v.z; x[q*4+3]=v.w;
            float4 w = cp[q]; c[q*4+0]=w.x; c[q*4+1]=w.y; c[q*4+2]=w.z; c[q*4+3]=w.w;
        }
    }

    // out = WI1 @ x + bI1   [48]
    float out[DIM1];
#pragma unroll
    for (int j = 0; j < DIM1; j++) {
        float a = __ldg(&bI1[j]);
        const float* w = &WI1[j * DIM];
#pragma unroll
        for (int i = 0; i < DIM; i++) a += x[i] * __ldg(&w[i]);
        out[j] = a;
    }

    // op = WA1 @ out + bA1  [16]
    float op[DIM];
#pragma unroll
    for (int j = 0; j < DIM; j++) {
        float a = __ldg(&bA1[j]);
        const float* w = &WA1[j * DIM1];
#pragma unroll
        for (int i = 0; i < DIM1; i++) a += out[i] * __ldg(&w[i]);
        op[j] = a;
    }

    // h = silu(LN(WM1 @ [out, c, op] + bM1))
    float h[DIM1];
#pragma unroll
    for (int j = 0; j < DIM1; j++) {
        const float* w = &sM1[j * 80];
        float a = sb1[j];
#pragma unroll
        for (int i = 0; i < DIM1; i++) a += out[i] * w[i];
#pragma unroll
        for (int i = 0; i < DIM; i++)  a += c[i]  * w[48 + i];
#pragma unroll
        for (int i = 0; i < DIM; i++)  a += op[i] * w[64 + i];
        h[j] = a;
    }
    ln_silu(h, sg, sbt);

    // scores + top-3 (descending, first occurrence on ties)
    const float* tb = th + (size_t)b * TTH * DIM;
    float s0 = -3.0e38f, s1 = -3.0e38f, s2 = -3.0e38f;
    int   i0 = 0, i1 = 0, i2 = 0;
#pragma unroll
    for (int t = 0; t < TTH; t++) {
        float s = 0.f;
        const float* r = tb + t * DIM;
#pragma unroll
        for (int k = 0; k < DIM; k++) s += r[k] * op[k];
        if (s > s0)      { s2=s1; i2=i1; s1=s0; i1=i0; s0=s; i0=t; }
        else if (s > s1) { s2=s1; i2=i1; s1=s;  i1=t; }
        else if (s > s2) { s2=s;  i2=t; }
    }
    float tp[3][DIM];
    {
        const float* r0 = tb + i0 * DIM;
        const float* r1 = tb + i1 * DIM;
        const float* r2 = tb + i2 * DIM;
#pragma unroll
        for (int k = 0; k < DIM; k++) { tp[0][k]=r0[k]; tp[1][k]=r1[k]; tp[2][k]=r2[k]; }
    }

    // h2 = silu(LN(WM2 @ [h, tp_flat, c] + bM2))
    float h2[DIM1];
#pragma unroll
    for (int j = 0; j < DIM1; j++) {
        const float* w = &sM2[j * 112];
        float a = sb2[j];
#pragma unroll
        for (int i = 0; i < DIM1; i++) a += h[i] * w[i];
#pragma unroll
        for (int r = 0; r < 3; r++)
#pragma unroll
            for (int k = 0; k < DIM; k++) a += tp[r][k] * w[48 + r * DIM + k];
#pragma unroll
        for (int k = 0; k < DIM; k++) a += c[k] * w[96 + k];
        h2[j] = a;
    }
    ln_silu(h2, sg, sbt);

    // h3 = silu(LN(WM3 @ h2 + bM3))
    float h3[DIM1];
#pragma unroll
    for (int j = 0; j < DIM1; j++) {
        const float* w = &sM3[j * DIM1];
        float a = sb3[j];
#pragma unroll
        for (int i = 0; i < DIM1; i++) a += h2[i] * w[i];
        h3[j] = a;
    }
    ln_silu(h3, sg, sbt);

    // o = WO1 @ h3 + bO1 -> g_o
#pragma unroll
    for (int j = 0; j < DIM; j++) {
        float a = __ldg(&bO1[j]);
        const float* w = &WO1[j * DIM1];
#pragma unroll
        for (int i = 0; i < DIM1; i++) a += h3[i] * __ldg(&w[i]);
        g_o[b * DIM + j] = a;
    }
}

// ---------------------------------------------------------------------------
// Stage 2: logits GEMM  [8192,16] x [16,32000] -> [8192,32000]
// Block tile: 64 batch x 256 vocab. Thread tile: 8 x 8 (f32x2 packed).
// ---------------------------------------------------------------------------
__global__ __launch_bounds__(256, 2) void k_gemm(float* __restrict__ out)
{
    __shared__ float es[DIM][256];   // E tile  [k][vocab]
    __shared__ float os[DIM][64];    // o tile  [k][batch]

    const int tid = threadIdx.x;
    const int e0 = blockIdx.x * 256;
    const int b0 = blockIdx.y * 64;

    // Load E tile (4096 floats) coalesced
#pragma unroll
    for (int q = 0; q < 4; q++) {
        int f4 = tid + q * 256;           // float4 index 0..1023
        int k  = f4 >> 6;
        int j4 = f4 & 63;
        *(float4*)&es[k][j4 * 4] =
            *(const float4*)&g_et[k * VOCAB + e0 + j4 * 4];
    }
    // Load + transpose o tile
    if (tid < 64) {
        const float4* orow = (const float4*)&g_o[(b0 + tid) * DIM];
        float4 r0 = orow[0], r1 = orow[1], r2 = orow[2], r3 = orow[3];
        os[0][tid]=r0.x;  os[1][tid]=r0.y;  os[2][tid]=r0.z;  os[3][tid]=r0.w;
        os[4][tid]=r1.x;  os[5][tid]=r1.y;  os[6][tid]=r1.z;  os[7][tid]=r1.w;
        os[8][tid]=r2.x;  os[9][tid]=r2.y;  os[10][tid]=r2.z; os[11][tid]=r2.w;
        os[12][tid]=r3.x; os[13][tid]=r3.y; os[14][tid]=r3.z; os[15][tid]=r3.w;
    }
    __syncthreads();

    const int tx = tid & 31;   // vocab: cols tx*4..+3 and 128+tx*4..+3
    const int ty = tid >> 5;   // batch: rows b0 + ty*8 .. +7

    unsigned long long acc[8][4];
#pragma unroll
    for (int m = 0; m < 8; m++)
#pragma unroll
        for (int n = 0; n < 4; n++) acc[m][n] = 0ull;

#pragma unroll
    for (int k = 0; k < DIM; k++) {
        ulonglong2 eA = *(const ulonglong2*)&es[k][tx * 4];        // conflict-free
        ulonglong2 eB = *(const ulonglong2*)&es[k][128 + tx * 4];  // conflict-free
        float4 oA = *(const float4*)&os[k][ty * 8];                // broadcast
        float4 oB = *(const float4*)&os[k][ty * 8 + 4];            // broadcast
        float ov[8] = {oA.x, oA.y, oA.z, oA.w, oB.x, oB.y, oB.z, oB.w};
#pragma unroll
        for (int m = 0; m < 8; m++) {
            unsigned long long a = fdup(ov[m]);
            acc[m][0] = f2fma(a, eA.x, acc[m][0]);
            acc[m][1] = f2fma(a, eA.y, acc[m][1]);
            acc[m][2] = f2fma(a, eB.x, acc[m][2]);
            acc[m][3] = f2fma(a, eB.y, acc[m][3]);
        }
    }

#pragma unroll
    for (int m = 0; m < 8; m++) {
        size_t row = (size_t)(b0 + ty * 8 + m) * VOCAB;
        ulonglong2 s1; s1.x = acc[m][0]; s1.y = acc[m][1];
        ulonglong2 s2; s2.x = acc[m][2]; s2.y = acc[m][3];
        *(ulonglong2*)&out[row + e0 + tx * 4]       = s1;
        *(ulonglong2*)&out[row + e0 + 128 + tx * 4] = s2;
    }
}

// ---------------------------------------------------------------------------
extern "C" void kernel_launch(void* const* d_in, const int* in_sizes, int n_in,
                              void* d_out, int out_size) {
    const float* we  = (const float*)d_in[0];
    const float* ctx = (const float*)d_in[1];
    const float* th  = (const float*)d_in[2];
    const float* WI1 = (const float*)d_in[3];  const float* bI1 = (const float*)d_in[4];
    const float* WA1 = (const float*)d_in[5];  const float* bA1 = (const float*)d_in[6];
    const float* WM1 = (const float*)d_in[7];  const float* bM1 = (const float*)d_in[8];
    const float* WM2 = (const float*)d_in[9];  const float* bM2 = (const float*)d_in[10];
    const float* WM3 = (const float*)d_in[11]; const float* bM3 = (const float*)d_in[12];
    const float* lng = (const float*)d_in[13]; const float* lnb = (const float*)d_in[14];
    const float* WO1 = (const float*)d_in[15]; const float* bO1 = (const float*)d_in[16];
    const float* E   = (const float*)d_in[17];
    float* out = (float*)d_out;

    k_transpose<<<(DIM * VOCAB + 255) / 256, 256>>>(E);
    k_stage1<<<BATCH / 64, 64>>>(we, ctx, th, WI1, bI1, WA1, bA1, WM1, bM1,
                                 WM2, bM2, WM3, bM3, lng, lnb, WO1, bO1);
    dim3 grid(VOCAB / 256, BATCH / 64);
    k_gemm<<<grid, 256>>>(out);
}

// round 6
// speedup vs baseline: 2.1046x; 2.1046x over previous
#include <cuda_runtime.h>
#include <cuda_bf16.h>

#define BATCH 8192
#define DIM   16
#define DIM1  48
#define TTH   20
#define VOCAB 32000

// Scratch (no runtime allocation allowed)
__device__ float g_o[BATCH * DIM];        // stage-1 output o[b][k]

// ---------------------------------------------------------------------------
// packed f32x2 helpers
// ---------------------------------------------------------------------------
__device__ __forceinline__ unsigned long long f2fma(unsigned long long a,
                                                    unsigned long long b,
                                                    unsigned long long c) {
    unsigned long long d;
    asm("fma.rn.f32x2 %0, %1, %2, %3;" : "=l"(d) : "l"(a), "l"(b), "l"(c));
    return d;
}

// ---------------------------------------------------------------------------
// Stage 1: fused tiny MLP, one thread per batch row
// ---------------------------------------------------------------------------
__device__ __forceinline__ void ln_silu(float* h, const float* g, const float* bt) {
    float mu = 0.f;
#pragma unroll
    for (int i = 0; i < DIM1; i++) mu += h[i];
    mu *= (1.0f / DIM1);
    float var = 0.f;
#pragma unroll
    for (int i = 0; i < DIM1; i++) { float d = h[i] - mu; var += d * d; }
    var *= (1.0f / DIM1);
    float r = rsqrtf(var + 1e-5f);
#pragma unroll
    for (int i = 0; i < DIM1; i++) {
        float y = (h[i] - mu) * r * g[i] + bt[i];
        h[i] = y / (1.0f + expf(-y));
    }
}

__global__ __launch_bounds__(64) void k_stage1(
    const float* __restrict__ we,  const float* __restrict__ ctx,
    const float* __restrict__ th,
    const float* __restrict__ WI1, const float* __restrict__ bI1,
    const float* __restrict__ WA1, const float* __restrict__ bA1,
    const float* __restrict__ WM1, const float* __restrict__ bM1,
    const float* __restrict__ WM2, const float* __restrict__ bM2,
    const float* __restrict__ WM3, const float* __restrict__ bM3,
    const float* __restrict__ lng, const float* __restrict__ lnb,
    const float* __restrict__ WO1, const float* __restrict__ bO1)
{
    __shared__ float sM1[DIM1 * 80];
    __shared__ float sM2[DIM1 * 112];
    __shared__ float sM3[DIM1 * DIM1];
    __shared__ float sb1[DIM1], sb2[DIM1], sb3[DIM1], sg[DIM1], sbt[DIM1];

    int tid = threadIdx.x;
    for (int i = tid; i < DIM1 * 80;  i += 64) sM1[i] = WM1[i];
    for (int i = tid; i < DIM1 * 112; i += 64) sM2[i] = WM2[i];
    for (int i = tid; i < DIM1 * DIM1; i += 64) sM3[i] = WM3[i];
    if (tid < DIM1) {
        sb1[tid] = bM1[tid]; sb2[tid] = bM2[tid]; sb3[tid] = bM3[tid];
        sg[tid] = lng[tid];  sbt[tid] = lnb[tid];
    }
    __syncthreads();

    int b = blockIdx.x * 64 + tid;
    if (b >= BATCH) return;

    // load inputs
    float x[DIM], c[DIM];
    {
        const float4* xp = (const float4*)&we[b * DIM];
        const float4* cp = (const float4*)&ctx[b * DIM];
#pragma unroll
        for (int q = 0; q < 4; q++) {
            float4 v = xp[q]; x[q*4+0]=v.x; x[q*4+1]=v.y; x[q*4+2]=v.z; x[q*4+3]=v.w;
            float4 w = cp[q]; c[q*4+0]=w.x; c[q*4+1]=w.y; c[q*4+2]=w.z; c[q*4+3]=w.w;
        }
    }

    // out = WI1 @ x + bI1   [48]
    float out[DIM1];
#pragma unroll
    for (int j = 0; j < DIM1; j++) {
        float a = __ldg(&bI1[j]);
        const float* w = &WI1[j * DIM];
#pragma unroll
        for (int i = 0; i < DIM; i++) a += x[i] * __ldg(&w[i]);
        out[j] = a;
    }

    // op = WA1 @ out + bA1  [16]
    float op[DIM];
#pragma unroll
    for (int j = 0; j < DIM; j++) {
        float a = __ldg(&bA1[j]);
        const float* w = &WA1[j * DIM1];
#pragma unroll
        for (int i = 0; i < DIM1; i++) a += out[i] * __ldg(&w[i]);
        op[j] = a;
    }

    // h = silu(LN(WM1 @ [out, c, op] + bM1))
    float h[DIM1];
#pragma unroll
    for (int j = 0; j < DIM1; j++) {
        const float* w = &sM1[j * 80];
        float a = sb1[j];
#pragma unroll
        for (int i = 0; i < DIM1; i++) a += out[i] * w[i];
#pragma unroll
        for (int i = 0; i < DIM; i++)  a += c[i]  * w[48 + i];
#pragma unroll
        for (int i = 0; i < DIM; i++)  a += op[i] * w[64 + i];
        h[j] = a;
    }
    ln_silu(h, sg, sbt);

    // scores + top-3 (descending, first occurrence on ties)
    const float* tb = th + (size_t)b * TTH * DIM;
    float s0 = -3.0e38f, s1 = -3.0e38f, s2 = -3.0e38f;
    int   i0 = 0, i1 = 0, i2 = 0;
#pragma unroll
    for (int t = 0; t < TTH; t++) {
        float s = 0.f;
        const float* r = tb + t * DIM;
#pragma unroll
        for (int k = 0; k < DIM; k++) s += r[k] * op[k];
        if (s > s0)      { s2=s1; i2=i1; s1=s0; i1=i0; s0=s; i0=t; }
        else if (s > s1) { s2=s1; i2=i1; s1=s;  i1=t; }
        else if (s > s2) { s2=s;  i2=t; }
    }
    float tp[3][DIM];
    {
        const float* r0 = tb + i0 * DIM;
        const float* r1 = tb + i1 * DIM;
        const float* r2 = tb + i2 * DIM;
#pragma unroll
        for (int k = 0; k < DIM; k++) { tp[0][k]=r0[k]; tp[1][k]=r1[k]; tp[2][k]=r2[k]; }
    }

    // h2 = silu(LN(WM2 @ [h, tp_flat, c] + bM2))
    float h2[DIM1];
#pragma unroll
    for (int j = 0; j < DIM1; j++) {
        const float* w = &sM2[j * 112];
        float a = sb2[j];
#pragma unroll
        for (int i = 0; i < DIM1; i++) a += h[i] * w[i];
#pragma unroll
        for (int r = 0; r < 3; r++)
#pragma unroll
            for (int k = 0; k < DIM; k++) a += tp[r][k] * w[48 + r * DIM + k];
#pragma unroll
        for (int k = 0; k < DIM; k++) a += c[k] * w[96 + k];
        h2[j] = a;
    }
    ln_silu(h2, sg, sbt);

    // h3 = silu(LN(WM3 @ h2 + bM3))
    float h3[DIM1];
#pragma unroll
    for (int j = 0; j < DIM1; j++) {
        const float* w = &sM3[j * DIM1];
        float a = sb3[j];
#pragma unroll
        for (int i = 0; i < DIM1; i++) a += h2[i] * w[i];
        h3[j] = a;
    }
    ln_silu(h3, sg, sbt);

    // o = WO1 @ h3 + bO1 -> g_o
#pragma unroll
    for (int j = 0; j < DIM; j++) {
        float a = __ldg(&bO1[j]);
        const float* w = &WO1[j * DIM1];
#pragma unroll
        for (int i = 0; i < DIM1; i++) a += h3[i] * __ldg(&w[i]);
        g_o[b * DIM + j] = a;
    }
}

// ---------------------------------------------------------------------------
// Stage 2: logits GEMM  [8192,16] x [16,32000] -> [8192,32000]
// Block tile: 64 batch x 128 vocab, 128 threads, 4 CTAs/SM.
// Thread tile: 8 batch x 8 vocab (f32x2 packed, FFMA2).
// E transpose folded into the tile load (E tile is contiguous in GMEM).
// ---------------------------------------------------------------------------
#define ES_STRIDE 132   // floats; 132*4 B = 528 B (16B-aligned rows), bank-skewed

__global__ __launch_bounds__(128, 4) void k_gemm(const float* __restrict__ E,
                                                 float* __restrict__ out)
{
    __shared__ float  es[DIM][ES_STRIDE];   // es[k][v]  (8.25 KB)
    __shared__ float2 os2[DIM][64];         // duplicated o pairs (8 KB)

    const int tid = threadIdx.x;
    const int v0 = blockIdx.x * 128;
    const int b0 = blockIdx.y * 64;

    // Load E tile rows v0..v0+127 (8 KB contiguous) and transpose into es.
    const float4* Eb = (const float4*)(E + (size_t)v0 * DIM);
#pragma unroll
    for (int q = 0; q < 4; q++) {
        int f = tid + q * 128;          // float4 index 0..511
        float4 v = Eb[f];
        int row = f >> 2;               // vocab row within tile
        int kc  = (f & 3) * 4;          // k-chunk
        es[kc + 0][row] = v.x;
        es[kc + 1][row] = v.y;
        es[kc + 2][row] = v.z;
        es[kc + 3][row] = v.w;
    }
    // Load o tile, store duplicated pairs for direct FFMA2 a-operand use.
    if (tid < 64) {
        const float4* orow = (const float4*)&g_o[(b0 + tid) * DIM];
#pragma unroll
        for (int q = 0; q < 4; q++) {
            float4 r = orow[q];
            os2[q * 4 + 0][tid] = make_float2(r.x, r.x);
            os2[q * 4 + 1][tid] = make_float2(r.y, r.y);
            os2[q * 4 + 2][tid] = make_float2(r.z, r.z);
            os2[q * 4 + 3][tid] = make_float2(r.w, r.w);
        }
    }
    __syncthreads();

    const int tx = tid & 15;    // vocab: cols tx*4..+3 and 64+tx*4..+3
    const int ty = tid >> 4;    // batch: rows b0 + ty*8 .. +7

    unsigned long long acc[8][4];
#pragma unroll
    for (int m = 0; m < 8; m++)
#pragma unroll
        for (int n = 0; n < 4; n++) acc[m][n] = 0ull;

#pragma unroll
    for (int k = 0; k < DIM; k++) {
        ulonglong2 eA = *(const ulonglong2*)&es[k][tx * 4];        // LDS.128
        ulonglong2 eB = *(const ulonglong2*)&es[k][64 + tx * 4];   // LDS.128
#pragma unroll
        for (int m = 0; m < 8; m++) {
            unsigned long long a =
                *(const unsigned long long*)&os2[k][ty * 8 + m];   // LDS.64 bcast
            acc[m][0] = f2fma(a, eA.x, acc[m][0]);
            acc[m][1] = f2fma(a, eA.y, acc[m][1]);
            acc[m][2] = f2fma(a, eB.x, acc[m][2]);
            acc[m][3] = f2fma(a, eB.y, acc[m][3]);
        }
    }

    union U { ulonglong2 u; float4 f; };
#pragma unroll
    for (int m = 0; m < 8; m++) {
        size_t row = (size_t)(b0 + ty * 8 + m) * VOCAB + v0;
        U u1; u1.u.x = acc[m][0]; u1.u.y = acc[m][1];
        U u2; u2.u.x = acc[m][2]; u2.u.y = acc[m][3];
        __stcs((float4*)&out[row + tx * 4],      u1.f);   // streaming store
        __stcs((float4*)&out[row + 64 + tx * 4], u2.f);
    }
}

// ---------------------------------------------------------------------------
extern "C" void kernel_launch(void* const* d_in, const int* in_sizes, int n_in,
                              void* d_out, int out_size) {
    const float* we  = (const float*)d_in[0];
    const float* ctx = (const float*)d_in[1];
    const float* th  = (const float*)d_in[2];
    const float* WI1 = (const float*)d_in[3];  const float* bI1 = (const float*)d_in[4];
    const float* WA1 = (const float*)d_in[5];  const float* bA1 = (const float*)d_in[6];
    const float* WM1 = (const float*)d_in[7];  const float* bM1 = (const float*)d_in[8];
    const float* WM2 = (const float*)d_in[9];  const float* bM2 = (const float*)d_in[10];
    const float* WM3 = (const float*)d_in[11]; const float* bM3 = (const float*)d_in[12];
    const float* lng = (const float*)d_in[13]; const float* lnb = (const float*)d_in[14];
    const float* WO1 = (const float*)d_in[15]; const float* bO1 = (const float*)d_in[16];
    const float* E   = (const float*)d_in[17];
    float* out = (float*)d_out;

    k_stage1<<<BATCH / 64, 64>>>(we, ctx, th, WI1, bI1, WA1, bA1, WM1, bM1,
                                 WM2, bM2, WM3, bM3, lng, lnb, WO1, bO1);
    dim3 grid(VOCAB / 128, BATCH / 64);
    k_gemm<<<grid, 128>>>(E, out);
}

// round 8
// speedup vs baseline: 2.6176x; 1.2437x over previous
#include <cuda_runtime.h>
#include <cuda_bf16.h>

#define BATCH 8192
#define DIM   16
#define DIM1  48
#define TTH   20
#define VOCAB 32000

// Scratch (no runtime allocation allowed)
__device__ float g_o[BATCH * DIM];        // stage-1 output o[b][k]

// ---------------------------------------------------------------------------
// packed f32x2 helpers
// ---------------------------------------------------------------------------
__device__ __forceinline__ unsigned long long f2fma(unsigned long long a,
                                                    unsigned long long b,
                                                    unsigned long long c) {
    unsigned long long d;
    asm("fma.rn.f32x2 %0, %1, %2, %3;" : "=l"(d) : "l"(a), "l"(b), "l"(c));
    return d;
}
__device__ __forceinline__ unsigned long long fdup(float x) {
    unsigned long long d;
    asm("mov.b64 %0, {%1, %1};" : "=l"(d) : "f"(x));
    return d;
}

// ---------------------------------------------------------------------------
// Stage 1: warp-per-row MLP. 512 threads (16 warps=16 rows) per block.
// All weights live transposed (i-major) in dynamic smem: at inner step i,
// lane j reads W_t[i*J + j] -> consecutive -> conflict-free.
// ---------------------------------------------------------------------------
// smem float offsets
#define O_WI1 0          // [16][48]
#define O_WA1 768        // [48][16]
#define O_WM1 1536       // [80][48]
#define O_WM2 5376       // [112][48]
#define O_WM3 10752      // [48][48]
#define O_WO1 13056      // [48][16]
#define O_B   13824      // biases: bI1@0 bA1@48 bM1@64 bM2@112 bM3@160 lng@208 lnb@256 bO1@304
#define O_WS  14144      // per-warp scratch: 16 warps * 192
#define SM_FLOATS 17216  // 68864 bytes

__device__ __forceinline__ float wredsum(float v) {
#pragma unroll
    for (int o = 16; o; o >>= 1) v += __shfl_xor_sync(0xffffffffu, v, o);
    return v;
}

// LayerNorm(48) + SiLU over values distributed: hA on all 32 lanes (j=lane),
// hB on lanes<16 (j=32+lane).
__device__ __forceinline__ void ln_silu_warp(float& hA, float& hB, int lane,
                                             const float* g, const float* bt) {
    float s = hA + (lane < 16 ? hB : 0.f);
    s = wredsum(s);
    float mu = s * (1.0f / DIM1);
    float dA = hA - mu, dB = hB - mu;
    float v = dA * dA + (lane < 16 ? dB * dB : 0.f);
    v = wredsum(v);
    float r = rsqrtf(v * (1.0f / DIM1) + 1e-5f);
    float yA = dA * r * g[lane] + bt[lane];
    hA = yA / (1.0f + __expf(-yA));
    if (lane < 16) {
        float yB = dB * r * g[32 + lane] + bt[32 + lane];
        hB = yB / (1.0f + __expf(-yB));
    }
}

__global__ __launch_bounds__(512) void k_stage1(
    const float* __restrict__ we,  const float* __restrict__ ctx,
    const float* __restrict__ th,
    const float* __restrict__ WI1, const float* __restrict__ bI1,
    const float* __restrict__ WA1, const float* __restrict__ bA1,
    const float* __restrict__ WM1, const float* __restrict__ bM1,
    const float* __restrict__ WM2, const float* __restrict__ bM2,
    const float* __restrict__ WM3, const float* __restrict__ bM3,
    const float* __restrict__ lng, const float* __restrict__ lnb,
    const float* __restrict__ WO1, const float* __restrict__ bO1)
{
    extern __shared__ float sm[];
    const int tid = threadIdx.x;

    // ---- load weights transposed into smem ----
    for (int idx = tid; idx < 768; idx += 512) {        // WI1t[16][48]
        int i = idx / 48, j = idx % 48;
        sm[O_WI1 + idx] = WI1[j * 16 + i];
    }
    for (int idx = tid; idx < 768; idx += 512) {        // WA1t[48][16]
        int i = idx / 16, j = idx % 16;
        sm[O_WA1 + idx] = WA1[j * 48 + i];
    }
    for (int idx = tid; idx < 3840; idx += 512) {       // WM1t[80][48]
        int i = idx / 48, j = idx % 48;
        sm[O_WM1 + idx] = WM1[j * 80 + i];
    }
    for (int idx = tid; idx < 5376; idx += 512) {       // WM2t[112][48]
        int i = idx / 48, j = idx % 48;
        sm[O_WM2 + idx] = WM2[j * 112 + i];
    }
    for (int idx = tid; idx < 2304; idx += 512) {       // WM3t[48][48]
        int i = idx / 48, j = idx % 48;
        sm[O_WM3 + idx] = WM3[j * 48 + i];
    }
    for (int idx = tid; idx < 768; idx += 512) {        // WO1t[48][16]
        int i = idx / 16, j = idx % 16;
        sm[O_WO1 + idx] = WO1[j * 48 + i];
    }
    if (tid < 48)  sm[O_B + tid]        = bI1[tid];
    if (tid < 16)  sm[O_B + 48 + tid]   = bA1[tid];
    if (tid < 48)  sm[O_B + 64 + tid]   = bM1[tid];
    if (tid < 48)  sm[O_B + 112 + tid]  = bM2[tid];
    if (tid < 48)  sm[O_B + 160 + tid]  = bM3[tid];
    if (tid < 48)  sm[O_B + 208 + tid]  = lng[tid];
    if (tid < 48)  sm[O_B + 256 + tid]  = lnb[tid];
    if (tid < 16)  sm[O_B + 304 + tid]  = bO1[tid];
    __syncthreads();

    const int lane = tid & 31;
    const int w    = tid >> 5;
    const int b    = blockIdx.x * 16 + w;
    float* ws = sm + O_WS + w * 192;   // out[0..47] op[48..63] h[64..111] tp/h2[112..159] sc[160..179]
    const float* sG  = sm + O_B + 208;
    const float* sBt = sm + O_B + 256;

    // row inputs (uniform per warp -> broadcast loads)
    float x[DIM], c[DIM];
    {
        const float4* xp = (const float4*)(we  + (size_t)b * DIM);
        const float4* cp = (const float4*)(ctx + (size_t)b * DIM);
#pragma unroll
        for (int q = 0; q < 4; q++) {
            float4 vx = __ldg(&xp[q]); x[q*4+0]=vx.x; x[q*4+1]=vx.y; x[q*4+2]=vx.z; x[q*4+3]=vx.w;
            float4 vc = __ldg(&cp[q]); c[q*4+0]=vc.x; c[q*4+1]=vc.y; c[q*4+2]=vc.z; c[q*4+3]=vc.w;
        }
    }

    // ---- I1: out[48] ----
    {
        float a = sm[O_B + lane];
        float a2 = (lane < 16) ? sm[O_B + 32 + lane] : 0.f;
#pragma unroll
        for (int i = 0; i < DIM; i++) {
            a += sm[O_WI1 + i * 48 + lane] * x[i];
            if (lane < 16) a2 += sm[O_WI1 + i * 48 + 32 + lane] * x[i];
        }
        ws[lane] = a;
        if (lane < 16) ws[32 + lane] = a2;
    }
    __syncwarp();

    // ---- A1: op[16] ----
    if (lane < 16) {
        float a = sm[O_B + 48 + lane];
#pragma unroll
        for (int i = 0; i < DIM1; i++) a += sm[O_WA1 + i * 16 + lane] * ws[i];
        ws[48 + lane] = a;
    }
    __syncwarp();

    // ---- M1 + LN + SiLU -> h[48] ----
    {
        float hA = sm[O_B + 64 + lane];
        float hB = (lane < 16) ? sm[O_B + 64 + 32 + lane] : 0.f;
#pragma unroll
        for (int i = 0; i < DIM1; i++) {
            float vi = ws[i];
            hA += sm[O_WM1 + i * 48 + lane] * vi;
            if (lane < 16) hB += sm[O_WM1 + i * 48 + 32 + lane] * vi;
        }
#pragma unroll
        for (int i = 0; i < DIM; i++) {
            hA += sm[O_WM1 + (48 + i) * 48 + lane] * c[i];
            if (lane < 16) hB += sm[O_WM1 + (48 + i) * 48 + 32 + lane] * c[i];
        }
#pragma unroll
        for (int i = 0; i < DIM; i++) {
            float vi = ws[48 + i];
            hA += sm[O_WM1 + (64 + i) * 48 + lane] * vi;
            if (lane < 16) hB += sm[O_WM1 + (64 + i) * 48 + 32 + lane] * vi;
        }
        ln_silu_warp(hA, hB, lane, sG, sBt);
        ws[64 + lane] = hA;
        if (lane < 16) ws[96 + lane] = hB;
    }
    __syncwarp();

    // ---- scores ----
    if (lane < TTH) {
        const float4* tr = (const float4*)(th + (size_t)b * TTH * DIM + lane * DIM);
        float s = 0.f;
#pragma unroll
        for (int q = 0; q < 4; q++) {
            float4 v = __ldg(&tr[q]);
            s += v.x * ws[48 + q*4+0] + v.y * ws[48 + q*4+1]
               + v.z * ws[48 + q*4+2] + v.w * ws[48 + q*4+3];
        }
        ws[160 + lane] = s;
    }
    __syncwarp();

    // ---- top-3 (replicated per lane; identical compare chain to reference) ----
    float s0 = -3.0e38f, s1 = -3.0e38f, s2 = -3.0e38f;
    int   i0 = 0, i1 = 0, i2 = 0;
#pragma unroll
    for (int t = 0; t < TTH; t++) {
        float s = ws[160 + t];
        if (s > s0)      { s2=s1; i2=i1; s1=s0; i1=i0; s0=s; i0=t; }
        else if (s > s1) { s2=s1; i2=i1; s1=s;  i1=t; }
        else if (s > s2) { s2=s;  i2=t; }
    }
    if (lane < 16) {
        const float* tb = th + (size_t)b * TTH * DIM;
        ws[112 + lane] = __ldg(&tb[i0 * DIM + lane]);
        ws[128 + lane] = __ldg(&tb[i1 * DIM + lane]);
        ws[144 + lane] = __ldg(&tb[i2 * DIM + lane]);
    }
    __syncwarp();

    // ---- M2 + LN + SiLU -> h2 ----
    float h2A, h2B;
    {
        float hA = sm[O_B + 112 + lane];
        float hB = (lane < 16) ? sm[O_B + 112 + 32 + lane] : 0.f;
#pragma unroll
        for (int i = 0; i < DIM1; i++) {
            float vi = ws[64 + i];
            hA += sm[O_WM2 + i * 48 + lane] * vi;
            if (lane < 16) hB += sm[O_WM2 + i * 48 + 32 + lane] * vi;
        }
#pragma unroll
        for (int i = 0; i < DIM1; i++) {
            float vi = ws[112 + i];
            hA += sm[O_WM2 + (48 + i) * 48 + lane] * vi;
            if (lane < 16) hB += sm[O_WM2 + (48 + i) * 48 + 32 + lane] * vi;
        }
#pragma unroll
        for (int i = 0; i < DIM; i++) {
            hA += sm[O_WM2 + (96 + i) * 48 + lane] * c[i];
            if (lane < 16) hB += sm[O_WM2 + (96 + i) * 48 + 32 + lane] * c[i];
        }
        ln_silu_warp(hA, hB, lane, sG, sBt);
        h2A = hA; h2B = hB;
    }
    __syncwarp();                 // everyone done reading ws[112..159] (tp)
    ws[112 + lane] = h2A;
    if (lane < 16) ws[144 + lane] = h2B;
    __syncwarp();

    // ---- M3 + LN + SiLU -> h3 ----
    float h3A, h3B;
    {
        float hA = sm[O_B + 160 + lane];
        float hB = (lane < 16) ? sm[O_B + 160 + 32 + lane] : 0.f;
#pragma unroll
        for (int i = 0; i < DIM1; i++) {
            float vi = ws[112 + i];
            hA += sm[O_WM3 + i * 48 + lane] * vi;
            if (lane < 16) hB += sm[O_WM3 + i * 48 + 32 + lane] * vi;
        }
        ln_silu_warp(hA, hB, lane, sG, sBt);
        h3A = hA; h3B = hB;
    }
    ws[lane] = h3A;               // slot 0..47 free (out no longer needed)
    if (lane < 16) ws[32 + lane] = h3B;
    __syncwarp();

    // ---- O1 -> g_o ----
    if (lane < 16) {
        float a = sm[O_B + 304 + lane];
#pragma unroll
        for (int i = 0; i < DIM1; i++) a += sm[O_WO1 + i * 16 + lane] * ws[i];
        g_o[(size_t)b * DIM + lane] = a;
    }
}

// ---------------------------------------------------------------------------
// Stage 2: logits GEMM  [8192,16] x [16,32000] -> [8192,32000]
// Block tile: 64 batch x 128 vocab, 128 threads, 4 CTAs/SM.
// Thread tile: 8 batch x 8 vocab (f32x2 packed, FFMA2).
// o tile as plain floats: per k-step 2 broadcast LDS.128 + register fdup
// (moves traffic off the saturated L1 pipe onto the idle ALU pipe).
// ---------------------------------------------------------------------------
#define ES_STRIDE 132   // floats; bank-skewed rows

__global__ __launch_bounds__(128, 4) void k_gemm(const float* __restrict__ E,
                                                 float* __restrict__ out)
{
    __shared__ float es[DIM][ES_STRIDE];   // es[k][v]
    __shared__ float os[DIM][64];          // os[k][b]

    const int tid = threadIdx.x;
    const int v0 = blockIdx.x * 128;
    const int b0 = blockIdx.y * 64;

    // Load E tile rows v0..v0+127 (8 KB contiguous) and transpose into es.
    const float4* Eb = (const float4*)(E + (size_t)v0 * DIM);
#pragma unroll
    for (int q = 0; q < 4; q++) {
        int f = tid + q * 128;          // float4 index 0..511
        float4 v = Eb[f];
        int row = f >> 2;               // vocab row within tile
        int kc  = (f & 3) * 4;          // k-chunk
        es[kc + 0][row] = v.x;
        es[kc + 1][row] = v.y;
        es[kc + 2][row] = v.z;
        es[kc + 3][row] = v.w;
    }
    // Load o tile (plain floats, transposed)
    if (tid < 64) {
        const float4* orow = (const float4*)&g_o[(size_t)(b0 + tid) * DIM];
#pragma unroll
        for (int q = 0; q < 4; q++) {
            float4 r = orow[q];
            os[q * 4 + 0][tid] = r.x;
            os[q * 4 + 1][tid] = r.y;
            os[q * 4 + 2][tid] = r.z;
            os[q * 4 + 3][tid] = r.w;
        }
    }
    __syncthreads();

    const int tx = tid & 15;    // vocab: cols tx*4..+3 and 64+tx*4..+3
    const int ty = tid >> 4;    // batch: rows b0 + ty*8 .. +7

    unsigned long long acc[8][4];
#pragma unroll
    for (int m = 0; m < 8; m++)
#pragma unroll
        for (int n = 0; n < 4; n++) acc[m][n] = 0ull;

#pragma unroll
    for (int k = 0; k < DIM; k++) {
        ulonglong2 eA = *(const ulonglong2*)&es[k][tx * 4];        // LDS.128
        ulonglong2 eB = *(const ulonglong2*)&es[k][64 + tx * 4];   // LDS.128
        float4 oA = *(const float4*)&os[k][ty * 8];                // LDS.128 bcast
        float4 oB = *(const float4*)&os[k][ty * 8 + 4];            // LDS.128 bcast
        unsigned long long a0 = fdup(oA.x), a1 = fdup(oA.y);
        unsigned long long a2 = fdup(oA.z), a3 = fdup(oA.w);
        unsigned long long a4 = fdup(oB.x), a5 = fdup(oB.y);
        unsigned long long a6 = fdup(oB.z), a7 = fdup(oB.w);
        unsigned long long av[8] = {a0, a1, a2, a3, a4, a5, a6, a7};
#pragma unroll
        for (int m = 0; m < 8; m++) {
            acc[m][0] = f2fma(av[m], eA.x, acc[m][0]);
            acc[m][1] = f2fma(av[m], eA.y, acc[m][1]);
            acc[m][2] = f2fma(av[m], eB.x, acc[m][2]);
            acc[m][3] = f2fma(av[m], eB.y, acc[m][3]);
        }
    }

    union U { ulonglong2 u; float4 f; };
#pragma unroll
    for (int m = 0; m < 8; m++) {
        size_t row = (size_t)(b0 + ty * 8 + m) * VOCAB + v0;
        U u1; u1.u.x = acc[m][0]; u1.u.y = acc[m][1];
        U u2; u2.u.x = acc[m][2]; u2.u.y = acc[m][3];
        __stcs((float4*)&out[row + tx * 4],      u1.f);   // streaming store
        __stcs((float4*)&out[row + 64 + tx * 4], u2.f);
    }
}

// ---------------------------------------------------------------------------
extern "C" void kernel_launch(void* const* d_in, const int* in_sizes, int n_in,
                              void* d_out, int out_size) {
    const float* we  = (const float*)d_in[0];
    const float* ctx = (const float*)d_in[1];
    const float* th  = (const float*)d_in[2];
    const float* WI1 = (const float*)d_in[3];  const float* bI1 = (const float*)d_in[4];
    const float* WA1 = (const float*)d_in[5];  const float* bA1 = (const float*)d_in[6];
    const float* WM1 = (const float*)d_in[7];  const float* bM1 = (const float*)d_in[8];
    const float* WM2 = (const float*)d_in[9];  const float* bM2 = (const float*)d_in[10];
    const float* WM3 = (const float*)d_in[11]; const float* bM3 = (const float*)d_in[12];
    const float* lng = (const float*)d_in[13]; const float* lnb = (const float*)d_in[14];
    const float* WO1 = (const float*)d_in[15]; const float* bO1 = (const float*)d_in[16];
    const float* E   = (const float*)d_in[17];
    float* out = (float*)d_out;

    // Unconditional (no static guard): deterministic, idempotent, capture-safe.
    cudaFuncSetAttribute(k_stage1, cudaFuncAttributeMaxDynamicSharedMemorySize,
                         SM_FLOATS * 4);

    k_stage1<<<BATCH / 16, 512, SM_FLOATS * 4>>>(we, ctx, th, WI1, bI1, WA1, bA1,
                                                 WM1, bM1, WM2, bM2, WM3, bM3,
                                                 lng, lnb, WO1, bO1);
    dim3 grid(VOCAB / 128, BATCH / 64);
    k_gemm<<<grid, 128>>>(E, out);
}